// round 16
// baseline (speedup 1.0000x reference)
#include <cuda_runtime.h>
#include <cuda_bf16.h>
#include <cstdint>

#define BATCH 2
#define CCH   128
#define NSEQ  8192
#define MSEL  2048

// ---------------- f32x2 packed helpers (sm_103a FFMA2 — PTX only) ----------------
__device__ __forceinline__ unsigned long long pack2(float lo, float hi) {
    unsigned long long r;
    asm("mov.b64 %0, {%1,%2};" : "=l"(r) : "f"(lo), "f"(hi));
    return r;
}
__device__ __forceinline__ void unpack2(unsigned long long v, float& lo, float& hi) {
    asm("mov.b64 {%0,%1}, %2;" : "=f"(lo), "=f"(hi) : "l"(v));
}
__device__ __forceinline__ void fma2(unsigned long long& d, unsigned long long a, unsigned long long b) {
    asm("fma.rn.f32x2 %0, %1, %2, %0;" : "+l"(d) : "l"(a), "l"(b));
}

// ---------------- sm_80-era tensor helpers (compute_103-safe, layouts validated) ----------------
__device__ __forceinline__ uint32_t smem_u32(const void* p) {
    uint32_t a;
    asm("{ .reg .u64 t; cvta.to.shared.u64 t, %1; cvt.u32.u64 %0, t; }" : "=r"(a) : "l"(p));
    return a;
}
__device__ __forceinline__ void ldsm_x4(uint32_t* r, uint32_t addr) {
    asm volatile("ldmatrix.sync.aligned.m8n8.x4.shared.b16 {%0,%1,%2,%3}, [%4];"
                 : "=r"(r[0]), "=r"(r[1]), "=r"(r[2]), "=r"(r[3]) : "r"(addr));
}
__device__ __forceinline__ void ldsm_x2(uint32_t* r, uint32_t addr) {
    asm volatile("ldmatrix.sync.aligned.m8n8.x2.shared.b16 {%0,%1}, [%2];"
                 : "=r"(r[0]), "=r"(r[1]) : "r"(addr));
}
__device__ __forceinline__ void mma_bf16(float* c, const uint32_t* a, const uint32_t* b) {
    asm volatile("mma.sync.aligned.m16n8k16.row.col.f32.bf16.bf16.f32 "
                 "{%0,%1,%2,%3}, {%4,%5,%6,%7}, {%8,%9}, {%0,%1,%2,%3};"
                 : "+f"(c[0]), "+f"(c[1]), "+f"(c[2]), "+f"(c[3])
                 : "r"(a[0]), "r"(a[1]), "r"(a[2]), "r"(a[3]), "r"(b[0]), "r"(b[1]));
}
// split f32x4 -> bf16 hi/lo 8-byte packets
__device__ __forceinline__ void split4(float4 v, uint2& hi, uint2& lo) {
    __nv_bfloat16 h0 = __float2bfloat16(v.x), h1 = __float2bfloat16(v.y);
    __nv_bfloat16 h2 = __float2bfloat16(v.z), h3 = __float2bfloat16(v.w);
    __nv_bfloat16 l0 = __float2bfloat16(v.x - __bfloat162float(h0));
    __nv_bfloat16 l1 = __float2bfloat16(v.y - __bfloat162float(h1));
    __nv_bfloat16 l2 = __float2bfloat16(v.z - __bfloat162float(h2));
    __nv_bfloat16 l3 = __float2bfloat16(v.w - __bfloat162float(h3));
    unsigned short hs0 = *reinterpret_cast<unsigned short*>(&h0);
    unsigned short hs1 = *reinterpret_cast<unsigned short*>(&h1);
    unsigned short hs2 = *reinterpret_cast<unsigned short*>(&h2);
    unsigned short hs3 = *reinterpret_cast<unsigned short*>(&h3);
    unsigned short ls0 = *reinterpret_cast<unsigned short*>(&l0);
    unsigned short ls1 = *reinterpret_cast<unsigned short*>(&l1);
    unsigned short ls2 = *reinterpret_cast<unsigned short*>(&l2);
    unsigned short ls3 = *reinterpret_cast<unsigned short*>(&l3);
    hi.x = (unsigned)hs0 | ((unsigned)hs1 << 16);
    hi.y = (unsigned)hs2 | ((unsigned)hs3 << 16);
    lo.x = (unsigned)ls0 | ((unsigned)ls1 << 16);
    lo.y = (unsigned)ls2 | ((unsigned)ls3 << 16);
}

// ---------------- scratch (static device globals; no allocation) ----------------
__device__ float g_qT[(size_t)BATCH * NSEQ * CCH];       // [b][n][c]
__device__ float g_kT[(size_t)BATCH * NSEQ * CCH];       // [b][m][c]
__device__ float g_v [(size_t)BATCH * CCH * NSEQ];       // [b][c][n]
__device__ float g_att[(size_t)BATCH * NSEQ * NSEQ];     // logits, then attention [b][n][m]
__device__ float g_sel[BATCH * NSEQ];                    // selection (XLA-order col sums)
__device__ int   g_idx[BATCH * MSEL];
__device__ float g_opart[(size_t)BATCH * 8 * CCH * MSEL];// K-split partials for output

// ---------------- dummy (aligns ncu capture slot onto energy_kernel) ----------------
__global__ void dummy_kernel() {}

// ---------------- K1: q,k,v projections (ascending-c fma chains) ----------------
__global__ __launch_bounds__(256) void qkv_kernel(const float* __restrict__ x,
                                                  const float* __restrict__ Wq,
                                                  const float* __restrict__ Wk,
                                                  const float* __restrict__ Wv) {
    __shared__ float xs[CCH][64];
    const int b  = blockIdx.y;
    const int n0 = blockIdx.x * 64;
    const float* xb = x + (size_t)b * CCH * NSEQ;

    for (int e4 = threadIdx.x; e4 < CCH * 16; e4 += 256) {
        int ci = e4 >> 4, k4 = e4 & 15;
        float4 v = *reinterpret_cast<const float4*>(xb + (size_t)ci * NSEQ + n0 + k4 * 4);
        xs[ci][k4 * 4 + 0] = v.x; xs[ci][k4 * 4 + 1] = v.y;
        xs[ci][k4 * 4 + 2] = v.z; xs[ci][k4 * 4 + 3] = v.w;
    }
    __syncthreads();

    for (int o = threadIdx.x; o < CCH * 64; o += 256) {
        int co = o >> 6, n = o & 63;
        const float* wq = Wq + co * CCH;
        const float* wk = Wk + co * CCH;
        const float* wv = Wv + co * CCH;
        float aq = 0.f, ak = 0.f, av = 0.f;
#pragma unroll 8
        for (int ci = 0; ci < CCH; ci++) {      // strict ascending-c chain
            float xv = xs[ci][n];
            aq = fmaf(wq[ci], xv, aq);
            ak = fmaf(wk[ci], xv, ak);
            av = fmaf(wv[ci], xv, av);
        }
        g_v[((size_t)b * CCH + co) * NSEQ + n0 + n] = av;
        size_t tr = ((size_t)b * NSEQ + n0 + n) * CCH + co;
        g_qT[tr] = aq;
        g_kT[tr] = ak;
    }
}

// ---------------- K2: energy GEMM, bit-exact FFMA2, batched chunk loads ----------------
// Same arithmetic as R11 (ascending-k chain per logit). All 24 LDS.128 per chunk
// issued up-front -> one scoreboard wait instead of eight exposed LDS latencies.
#define AS_STRIDE 260
#define K2_SMEM ((128 * AS_STRIDE + 128 * 132) * 4)
__global__ __launch_bounds__(256, 1) void energy_kernel() {
    extern __shared__ float sm[];
    float* As = sm;                          // packed row-pairs [128][AS_STRIDE]
    float* Bs = sm + 128 * AS_STRIDE;        // row-major [128][132]
    const int b  = blockIdx.z;
    const int n0 = blockIdx.y * 256;
    const int m0 = blockIdx.x * 128;
    const int tid = threadIdx.x;

    const float* Ag = g_qT + ((size_t)b * NSEQ + n0) * CCH;
    const float* Bg = g_kT + ((size_t)b * NSEQ + m0) * CCH;
    for (int e4 = tid; e4 < 256 * 32; e4 += 256) {
        int r = e4 >> 5, c4 = e4 & 31;
        float4 va = *reinterpret_cast<const float4*>(Ag + r * CCH + c4 * 4);
        float* ap = As + (r & 127) * AS_STRIDE + (r >> 7);
        ap[(c4 * 4 + 0) * 2] = va.x; ap[(c4 * 4 + 1) * 2] = va.y;
        ap[(c4 * 4 + 2) * 2] = va.z; ap[(c4 * 4 + 3) * 2] = va.w;
        if (r < 128) {
            float4 vb = *reinterpret_cast<const float4*>(Bg + r * CCH + c4 * 4);
            *reinterpret_cast<float4*>(&Bs[r * 132 + c4 * 4]) = vb;
        }
    }
    __syncthreads();

    const int tx = tid & 15, tyy = tid >> 4;   // 16 x 16
    unsigned long long acc2[8][8];
#pragma unroll
    for (int i = 0; i < 8; i++)
#pragma unroll
        for (int j = 0; j < 8; j++) acc2[i][j] = 0ull;

#pragma unroll 1
    for (int k = 0; k < 128; k += 4) {
        float4 av[8][2];
        float4 bv[8];
        // batched loads: 16 A + 8 B LDS.128 back-to-back (MLP), single wait
#pragma unroll
        for (int i2 = 0; i2 < 8; i2++) {
            const float4* ap = reinterpret_cast<const float4*>(As + (tyy + 16 * i2) * AS_STRIDE + 2 * k);
            av[i2][0] = ap[0];
            av[i2][1] = ap[1];
        }
#pragma unroll
        for (int j = 0; j < 8; j++)
            bv[j] = *reinterpret_cast<const float4*>(&Bs[(tx + 16 * j) * 132 + k]);

#pragma unroll
        for (int j = 0; j < 8; j++) {
            unsigned long long b0 = pack2(bv[j].x, bv[j].x);
            unsigned long long b1 = pack2(bv[j].y, bv[j].y);
            unsigned long long b2 = pack2(bv[j].z, bv[j].z);
            unsigned long long b3 = pack2(bv[j].w, bv[j].w);
#pragma unroll
            for (int i2 = 0; i2 < 8; i2++) {
                const unsigned long long* a = reinterpret_cast<const unsigned long long*>(&av[i2][0]);
                fma2(acc2[i2][j], a[0], b0);
                fma2(acc2[i2][j], a[1], b1);
                fma2(acc2[i2][j], a[2], b2);
                fma2(acc2[i2][j], a[3], b3);
            }
        }
    }

    const float sc = sqrtf(128.0f);
    float* out = g_att + ((size_t)b * NSEQ + n0) * NSEQ + m0;
#pragma unroll
    for (int i2 = 0; i2 < 8; i2++)
#pragma unroll
        for (int j = 0; j < 8; j++) {
            float lo, hi;
            unpack2(acc2[i2][j], lo, hi);
            out[(size_t)(tyy + 16 * i2)       * NSEQ + tx + 16 * j] = __fdiv_rn(lo, sc);
            out[(size_t)(tyy + 16 * i2 + 128) * NSEQ + tx + 16 * j] = __fdiv_rn(hi, sc);
        }
}

// ---------------- K3: softmax rows in place; Kahan f32 row sum (16 rows/CTA) ----------------
__global__ __launch_bounds__(256) void softmax_kernel() {
    __shared__ float rowbuf[NSEQ];   // 32KB
    __shared__ float  redf[8];
    __shared__ double redd[8];
    __shared__ float  s_rmax, s_S;

    const int b   = blockIdx.y;
    const int r0  = blockIdx.x * 16;
    const int tid = threadIdx.x;
    const int lane = tid & 31, wid = tid >> 5;

    for (int rr = 0; rr < 16; rr++) {
        const int row = r0 + rr;
        float* L = g_att + ((size_t)b * NSEQ + row) * NSEQ;

        float lmax = -3.0e38f;
        for (int e4 = tid; e4 < NSEQ / 4; e4 += 256) {
            float4 v = *reinterpret_cast<const float4*>(L + e4 * 4);
            *reinterpret_cast<float4*>(&rowbuf[e4 * 4]) = v;
            lmax = fmaxf(lmax, fmaxf(fmaxf(v.x, v.y), fmaxf(v.z, v.w)));
        }
#pragma unroll
        for (int o = 16; o; o >>= 1) lmax = fmaxf(lmax, __shfl_xor_sync(0xffffffffu, lmax, o));
        if (lane == 0) redf[wid] = lmax;
        __syncthreads();
        if (tid == 0) {
            float m = redf[0];
#pragma unroll
            for (int w = 1; w < 8; w++) m = fmaxf(m, redf[w]);
            s_rmax = m;
        }
        __syncthreads();
        const float rm = s_rmax;

        float ksum = 0.f, kc = 0.f;
        for (int e4 = tid; e4 < NSEQ / 4; e4 += 256) {
            float4 v = *reinterpret_cast<float4*>(&rowbuf[e4 * 4]);
            v.x = expf(v.x - rm); v.y = expf(v.y - rm);
            v.z = expf(v.z - rm); v.w = expf(v.w - rm);
            *reinterpret_cast<float4*>(&rowbuf[e4 * 4]) = v;
#pragma unroll
            for (int u = 0; u < 4; u++) {
                float val = (&v.x)[u];
                float y = __fsub_rn(val, kc);
                float t = __fadd_rn(ksum, y);
                kc = __fsub_rn(__fsub_rn(t, ksum), y);
                ksum = t;
            }
        }
        double lsum = (double)ksum + (double)kc;
#pragma unroll
        for (int o = 16; o; o >>= 1) lsum += __shfl_xor_sync(0xffffffffu, lsum, o);
        if (lane == 0) redd[wid] = lsum;
        __syncthreads();
        if (tid == 0) {
            double s = redd[0];
#pragma unroll
            for (int w = 1; w < 8; w++) s += redd[w];
            s_S = (float)s;
        }
        __syncthreads();
        const float Sf = s_S;

        for (int e4 = tid; e4 < NSEQ / 4; e4 += 256) {
            float4 p = *reinterpret_cast<float4*>(&rowbuf[e4 * 4]);
            p.x = __fdiv_rn(p.x, Sf); p.y = __fdiv_rn(p.y, Sf);
            p.z = __fdiv_rn(p.z, Sf); p.w = __fdiv_rn(p.w, Sf);
            *reinterpret_cast<float4*>(L + e4 * 4) = p;
        }
        __syncthreads();
    }
}

// ---------------- K3b: XLA-GPU two-stage column reduction replica (DO NOT TOUCH) ----------------
__global__ __launch_bounds__(1024) void colsum_kernel() {
    __shared__ float part[32][33];
    const int b  = blockIdx.y;
    const int m  = blockIdx.x * 32 + threadIdx.x;
    const int ty = threadIdx.y;
    const float* A = g_att + (size_t)b * NSEQ * NSEQ + m;

    float s[8];
#pragma unroll
    for (int p = 0; p < 8; p++) {
        float acc = 0.f;
#pragma unroll
        for (int k = 0; k < 32; k++)
            acc += A[(size_t)(p * 1024 + ty + 32 * k) * NSEQ];
        s[p] = acc;
    }

    float s1[8];
#pragma unroll
    for (int p = 0; p < 8; p++) {
        __syncthreads();
        part[ty][threadIdx.x] = s[p];
        __syncthreads();
        float q = part[threadIdx.x][ty];
#pragma unroll
        for (int off = 16; off; off >>= 1)
            q += __shfl_down_sync(0xffffffffu, q, off);
        s1[p] = q;
    }

    if (threadIdx.x == 0) {
        float r = ((s1[0] + s1[4]) + (s1[2] + s1[6]))
                + ((s1[1] + s1[5]) + (s1[3] + s1[7]));
        g_sel[b * NSEQ + blockIdx.x * 32 + ty] = r;
    }
}

// ---------------- K4: top-k (bitonic sort, desc value / asc index tie-break) ----------------
#define K4_SMEM (NSEQ * 8)
__global__ __launch_bounds__(1024) void topk_kernel() {
    extern __shared__ unsigned long long keys[];
    const int b = blockIdx.x;
    const int tid = threadIdx.x;

    for (int e = tid; e < NSEQ; e += 1024) {
        unsigned int u = __float_as_uint(g_sel[b * NSEQ + e]);
        u = (u & 0x80000000u) ? ~u : (u | 0x80000000u);
        u = ~u;
        keys[e] = ((unsigned long long)u << 32) | (unsigned int)e;
    }
    __syncthreads();

    for (int size = 2; size <= NSEQ; size <<= 1) {
        for (int stride = size >> 1; stride > 0; stride >>= 1) {
            for (int i = tid; i < NSEQ; i += 1024) {
                int j = i ^ stride;
                if (j > i) {
                    bool up = ((i & size) == 0);
                    unsigned long long a = keys[i], c = keys[j];
                    if ((a > c) == up) { keys[i] = c; keys[j] = a; }
                }
            }
            __syncthreads();
        }
    }

    for (int e = tid; e < MSEL; e += 1024)
        g_idx[b * MSEL + e] = (int)(keys[e] & 0xffffffffu);
}

// ---------------- K5: out = P @ V^T via HMMA, 2-way bf16 split x 3 products ----------------
#define ORS   144
#define OTILE (128 * ORS)               // 18432 bytes
#define OUT_SMEM (4 * OTILE)            // 73728
__global__ __launch_bounds__(256, 2) void out_hmma_kernel() {
    extern __shared__ char smem[];
    const uint32_t base = smem_u32(smem);
    __shared__ int srow[128];
    const int tid = threadIdx.x, wid = tid >> 5, lane = tid & 31;
    const int z  = blockIdx.z;           // b*8 + ks
    const int b  = z >> 3;
    const int ks = z & 7;
    const int j0 = blockIdx.x * 128;

    if (tid < 128) srow[tid] = g_idx[b * MSEL + j0 + tid];
    __syncthreads();

    const int wm = wid >> 2, wn = wid & 3;     // warp tile: 64(c) x 32(j)
    float acc[4][4][4];
#pragma unroll
    for (int mt = 0; mt < 4; mt++)
#pragma unroll
        for (int nt = 0; nt < 4; nt++)
#pragma unroll
            for (int i = 0; i < 4; i++) acc[mt][nt][i] = 0.f;

    const float* vb = g_v + (size_t)b * CCH * NSEQ;
    const float* Ab = g_att + (size_t)b * NSEQ * NSEQ;

    const int a_row = lane & 15, a_ch = lane >> 4;
    const int b_row = lane & 7,  b_ch = (lane >> 3) & 1;

    const int kbeg = ks * (NSEQ / 8);
#pragma unroll 1
    for (int k0 = kbeg; k0 < kbeg + NSEQ / 8; k0 += 64) {
        for (int idx = tid; idx < 2048; idx += 256) {
            int row = idx >> 4, c4 = idx & 15;
            float4 v = *reinterpret_cast<const float4*>(vb + (size_t)row * NSEQ + k0 + c4 * 4);
            uint2 vhi, vlo;
            split4(v, vhi, vlo);
            *reinterpret_cast<uint2*>(smem + 0 * OTILE + row * ORS + c4 * 8) = vhi;
            *reinterpret_cast<uint2*>(smem + 1 * OTILE + row * ORS + c4 * 8) = vlo;
            float4 p = *reinterpret_cast<const float4*>(Ab + (size_t)srow[row] * NSEQ + k0 + c4 * 4);
            uint2 phi, plo;
            split4(p, phi, plo);
            *reinterpret_cast<uint2*>(smem + 2 * OTILE + row * ORS + c4 * 8) = phi;
            *reinterpret_cast<uint2*>(smem + 3 * OTILE + row * ORS + c4 * 8) = plo;
        }
        __syncthreads();

        const int PV[3] = {0, 0, 1};
        const int PP[3] = {0, 1, 0};
#pragma unroll
        for (int pp = 0; pp < 3; pp++) {
            const uint32_t Vb = base + PV[pp] * OTILE;
            const uint32_t Pb = base + (2 + PP[pp]) * OTILE;
#pragma unroll
            for (int kk = 0; kk < 4; kk++) {
                uint32_t af[4][4], bfr[4][2];
#pragma unroll
                for (int mt = 0; mt < 4; mt++)
                    ldsm_x4(af[mt], Vb + (wm * 64 + mt * 16 + a_row) * ORS + kk * 32 + a_ch * 16);
#pragma unroll
                for (int nt = 0; nt < 4; nt++)
                    ldsm_x2(bfr[nt], Pb + (wn * 32 + nt * 8 + b_row) * ORS + kk * 32 + b_ch * 16);
#pragma unroll
                for (int mt = 0; mt < 4; mt++)
#pragma unroll
                    for (int nt = 0; nt < 4; nt++)
                        mma_bf16(acc[mt][nt], af[mt], bfr[nt]);
            }
        }
        __syncthreads();
    }

    float* op = g_opart + (size_t)z * CCH * MSEL;
#pragma unroll
    for (int mt = 0; mt < 4; mt++)
#pragma unroll
        for (int nt = 0; nt < 4; nt++) {
            int c  = wm * 64 + mt * 16 + (lane >> 2);
            int jj = j0 + wn * 32 + nt * 8 + (lane & 3) * 2;
            *reinterpret_cast<float2*>(op + (size_t)c * MSEL + jj) =
                make_float2(acc[mt][nt][0], acc[mt][nt][1]);
            *reinterpret_cast<float2*>(op + (size_t)(c + 8) * MSEL + jj) =
                make_float2(acc[mt][nt][2], acc[mt][nt][3]);
        }
}

// ---------------- K5b: combine K-split partials (8-way) ----------------
__global__ __launch_bounds__(256) void combine_kernel(float* __restrict__ out) {
    const int b = blockIdx.y;
    const size_t e4 = (size_t)blockIdx.x * 256 + threadIdx.x;
    float4 r = make_float4(0.f, 0.f, 0.f, 0.f);
#pragma unroll
    for (int p = 0; p < 8; p++) {
        const float4 v = reinterpret_cast<const float4*>(
            g_opart + (size_t)(b * 8 + p) * CCH * MSEL)[e4];
        r.x += v.x; r.y += v.y; r.z += v.z; r.w += v.w;
    }
    reinterpret_cast<float4*>(out + (size_t)b * CCH * MSEL)[e4] = r;
}

// ---------------- launch ----------------
extern "C" void kernel_launch(void* const* d_in, const int* in_sizes, int n_in,
                              void* d_out, int out_size) {
    const float* x  = (const float*)d_in[0];
    const float* Wq = (const float*)d_in[1];
    const float* Wk = (const float*)d_in[2];
    const float* Wv = (const float*)d_in[3];
    float* out = (float*)d_out;

    cudaFuncSetAttribute(energy_kernel,   cudaFuncAttributeMaxDynamicSharedMemorySize, K2_SMEM);
    cudaFuncSetAttribute(topk_kernel,     cudaFuncAttributeMaxDynamicSharedMemorySize, K4_SMEM);
    cudaFuncSetAttribute(out_hmma_kernel, cudaFuncAttributeMaxDynamicSharedMemorySize, OUT_SMEM);

    qkv_kernel<<<dim3(NSEQ / 64, BATCH), 256>>>(x, Wq, Wk, Wv);                       // 1
    dummy_kernel<<<1, 32>>>();                                                        // 2
    dummy_kernel<<<1, 32>>>();                                                        // 3
    energy_kernel<<<dim3(NSEQ / 128, NSEQ / 256, BATCH), 256, K2_SMEM>>>();           // 4 <- ncu slot
    softmax_kernel<<<dim3(NSEQ / 16, BATCH), 256>>>();                                // 5
    colsum_kernel<<<dim3(NSEQ / 32, BATCH), dim3(32, 32)>>>();                        // 6
    topk_kernel<<<BATCH, 1024, K4_SMEM>>>();                                          // 7
    out_hmma_kernel<<<dim3(MSEL / 128, 1, BATCH * 8), 256, OUT_SMEM>>>();             // 8
    combine_kernel<<<dim3(CCH * MSEL / 4 / 256, BATCH), 256>>>(out);                  // 9
}

// round 17
// speedup vs baseline: 1.0778x; 1.0778x over previous
#include <cuda_runtime.h>
#include <cuda_bf16.h>
#include <cstdint>

#define BATCH 2
#define CCH   128
#define NSEQ  8192
#define MSEL  2048

// ---------------- f32x2 packed helpers (sm_103a FFMA2 — PTX only) ----------------
__device__ __forceinline__ unsigned long long pack2(float lo, float hi) {
    unsigned long long r;
    asm("mov.b64 %0, {%1,%2};" : "=l"(r) : "f"(lo), "f"(hi));
    return r;
}
__device__ __forceinline__ void unpack2(unsigned long long v, float& lo, float& hi) {
    asm("mov.b64 {%0,%1}, %2;" : "=f"(lo), "=f"(hi) : "l"(v));
}
__device__ __forceinline__ void fma2(unsigned long long& d, unsigned long long a, unsigned long long b) {
    asm("fma.rn.f32x2 %0, %1, %2, %0;" : "+l"(d) : "l"(a), "l"(b));
}

// ---------------- sm_80-era tensor helpers (compute_103-safe, layouts validated) ----------------
__device__ __forceinline__ uint32_t smem_u32(const void* p) {
    uint32_t a;
    asm("{ .reg .u64 t; cvta.to.shared.u64 t, %1; cvt.u32.u64 %0, t; }" : "=r"(a) : "l"(p));
    return a;
}
__device__ __forceinline__ void ldsm_x4(uint32_t* r, uint32_t addr) {
    asm volatile("ldmatrix.sync.aligned.m8n8.x4.shared.b16 {%0,%1,%2,%3}, [%4];"
                 : "=r"(r[0]), "=r"(r[1]), "=r"(r[2]), "=r"(r[3]) : "r"(addr));
}
__device__ __forceinline__ void ldsm_x2(uint32_t* r, uint32_t addr) {
    asm volatile("ldmatrix.sync.aligned.m8n8.x2.shared.b16 {%0,%1}, [%2];"
                 : "=r"(r[0]), "=r"(r[1]) : "r"(addr));
}
__device__ __forceinline__ void mma_bf16(float* c, const uint32_t* a, const uint32_t* b) {
    asm volatile("mma.sync.aligned.m16n8k16.row.col.f32.bf16.bf16.f32 "
                 "{%0,%1,%2,%3}, {%4,%5,%6,%7}, {%8,%9}, {%0,%1,%2,%3};"
                 : "+f"(c[0]), "+f"(c[1]), "+f"(c[2]), "+f"(c[3])
                 : "r"(a[0]), "r"(a[1]), "r"(a[2]), "r"(a[3]), "r"(b[0]), "r"(b[1]));
}
// split f32x4 -> bf16 hi/lo 8-byte packets
__device__ __forceinline__ void split4(float4 v, uint2& hi, uint2& lo) {
    __nv_bfloat16 h0 = __float2bfloat16(v.x), h1 = __float2bfloat16(v.y);
    __nv_bfloat16 h2 = __float2bfloat16(v.z), h3 = __float2bfloat16(v.w);
    __nv_bfloat16 l0 = __float2bfloat16(v.x - __bfloat162float(h0));
    __nv_bfloat16 l1 = __float2bfloat16(v.y - __bfloat162float(h1));
    __nv_bfloat16 l2 = __float2bfloat16(v.z - __bfloat162float(h2));
    __nv_bfloat16 l3 = __float2bfloat16(v.w - __bfloat162float(h3));
    unsigned short hs0 = *reinterpret_cast<unsigned short*>(&h0);
    unsigned short hs1 = *reinterpret_cast<unsigned short*>(&h1);
    unsigned short hs2 = *reinterpret_cast<unsigned short*>(&h2);
    unsigned short hs3 = *reinterpret_cast<unsigned short*>(&h3);
    unsigned short ls0 = *reinterpret_cast<unsigned short*>(&l0);
    unsigned short ls1 = *reinterpret_cast<unsigned short*>(&l1);
    unsigned short ls2 = *reinterpret_cast<unsigned short*>(&l2);
    unsigned short ls3 = *reinterpret_cast<unsigned short*>(&l3);
    hi.x = (unsigned)hs0 | ((unsigned)hs1 << 16);
    hi.y = (unsigned)hs2 | ((unsigned)hs3 << 16);
    lo.x = (unsigned)ls0 | ((unsigned)ls1 << 16);
    lo.y = (unsigned)ls2 | ((unsigned)ls3 << 16);
}

// ---------------- scratch (static device globals; no allocation) ----------------
__device__ float g_qT[(size_t)BATCH * NSEQ * CCH];       // [b][n][c]
__device__ float g_kT[(size_t)BATCH * NSEQ * CCH];       // [b][m][c]
__device__ float g_v [(size_t)BATCH * CCH * NSEQ];       // [b][c][n]
__device__ float g_att[(size_t)BATCH * NSEQ * NSEQ];     // logits, then attention [b][n][m]
__device__ float g_sel[BATCH * NSEQ];                    // selection (XLA-order col sums)
__device__ int   g_idx[BATCH * MSEL];
__device__ float g_opart[(size_t)BATCH * 8 * CCH * MSEL];// K-split partials for output

// ---------------- dummy (aligns ncu capture slot #4 onto qkv this round) ----------------
__global__ void dummy_kernel() {}

// ---------------- K1: q,k,v projections as smem GEMM (bit-identical ascending-ci chains) ----------------
// CTA: 64 n-cols x 128 co, all 3 matrices. W staged in smem in 32-ci chunks.
#define WS_STRIDE 36
__global__ __launch_bounds__(256) void qkv_kernel(const float* __restrict__ x,
                                                  const float* __restrict__ Wq,
                                                  const float* __restrict__ Wk,
                                                  const float* __restrict__ Wv) {
    __shared__ float Ws[3][CCH][WS_STRIDE];   // 55.3KB, rows 144B (16B-aligned)
    __shared__ float xs[32][68];              // 8.7KB, rows 272B
    const int b  = blockIdx.y;
    const int n0 = blockIdx.x * 64;
    const int tid = threadIdx.x;
    const int tx = tid & 15;    // n quad
    const int ty = tid >> 4;    // co base

    float acc[3][8][4];
#pragma unroll
    for (int m = 0; m < 3; m++)
#pragma unroll
        for (int i = 0; i < 8; i++)
#pragma unroll
            for (int n = 0; n < 4; n++) acc[m][i][n] = 0.f;

    const float* xb = x + (size_t)b * CCH * NSEQ;

#pragma unroll 1
    for (int chunk = 0; chunk < 4; chunk++) {
        const int ci0 = chunk * 32;
        // stage W chunk: 3 x 128 co x 32 ci
        for (int e = tid; e < 3 * CCH * 8; e += 256) {
            int m = e >> 10, r = e & 1023, co = r >> 3, c4 = r & 7;
            const float* W = (m == 0) ? Wq : ((m == 1) ? Wk : Wv);
            float4 w = *reinterpret_cast<const float4*>(W + co * CCH + ci0 + c4 * 4);
            *reinterpret_cast<float4*>(&Ws[m][co][c4 * 4]) = w;
        }
        // stage x chunk: 32 ci x 64 n
        for (int e = tid; e < 512; e += 256) {
            int ci = e >> 4, nf = e & 15;
            float4 v = *reinterpret_cast<const float4*>(xb + (size_t)(ci0 + ci) * NSEQ + n0 + nf * 4);
            *reinterpret_cast<float4*>(&xs[ci][nf * 4]) = v;
        }
        __syncthreads();

#pragma unroll
        for (int q8 = 0; q8 < 8; q8++) {
            const int ci = q8 * 4;
            float4 xr[4];
#pragma unroll
            for (int j = 0; j < 4; j++)
                xr[j] = *reinterpret_cast<const float4*>(&xs[ci + j][tx * 4]);
#pragma unroll
            for (int m = 0; m < 3; m++)
#pragma unroll
                for (int i = 0; i < 8; i++) {
                    float4 w = *reinterpret_cast<const float4*>(&Ws[m][ty + 16 * i][ci]);
                    // ascending-ci chain per output (ci, ci+1, ci+2, ci+3)
                    acc[m][i][0] = fmaf(w.x, xr[0].x, acc[m][i][0]);
                    acc[m][i][1] = fmaf(w.x, xr[0].y, acc[m][i][1]);
                    acc[m][i][2] = fmaf(w.x, xr[0].z, acc[m][i][2]);
                    acc[m][i][3] = fmaf(w.x, xr[0].w, acc[m][i][3]);
                    acc[m][i][0] = fmaf(w.y, xr[1].x, acc[m][i][0]);
                    acc[m][i][1] = fmaf(w.y, xr[1].y, acc[m][i][1]);
                    acc[m][i][2] = fmaf(w.y, xr[1].z, acc[m][i][2]);
                    acc[m][i][3] = fmaf(w.y, xr[1].w, acc[m][i][3]);
                    acc[m][i][0] = fmaf(w.z, xr[2].x, acc[m][i][0]);
                    acc[m][i][1] = fmaf(w.z, xr[2].y, acc[m][i][1]);
                    acc[m][i][2] = fmaf(w.z, xr[2].z, acc[m][i][2]);
                    acc[m][i][3] = fmaf(w.z, xr[2].w, acc[m][i][3]);
                    acc[m][i][0] = fmaf(w.w, xr[3].x, acc[m][i][0]);
                    acc[m][i][1] = fmaf(w.w, xr[3].y, acc[m][i][1]);
                    acc[m][i][2] = fmaf(w.w, xr[3].z, acc[m][i][2]);
                    acc[m][i][3] = fmaf(w.w, xr[3].w, acc[m][i][3]);
                }
        }
        __syncthreads();
    }

    // writes: v coalesced float4; qT/kT transposed scalar
#pragma unroll
    for (int i = 0; i < 8; i++) {
        int co = ty + 16 * i;
        *reinterpret_cast<float4*>(g_v + ((size_t)b * CCH + co) * NSEQ + n0 + tx * 4) =
            make_float4(acc[2][i][0], acc[2][i][1], acc[2][i][2], acc[2][i][3]);
#pragma unroll
        for (int nn = 0; nn < 4; nn++) {
            size_t tr = ((size_t)b * NSEQ + n0 + tx * 4 + nn) * CCH + co;
            g_qT[tr] = acc[0][i][nn];
            g_kT[tr] = acc[1][i][nn];
        }
    }
}

// ---------------- K2: energy GEMM, bit-exact FFMA2 (best-measured R15 form) ----------------
#define AS_STRIDE 260
#define K2_SMEM ((128 * AS_STRIDE + 128 * 132) * 4)
__global__ __launch_bounds__(256, 1) void energy_kernel() {
    extern __shared__ float sm[];
    float* As = sm;                          // packed row-pairs [128][AS_STRIDE]
    float* Bs = sm + 128 * AS_STRIDE;        // row-major [128][132]
    const int b  = blockIdx.z;
    const int n0 = blockIdx.y * 256;
    const int m0 = blockIdx.x * 128;
    const int tid = threadIdx.x;

    const float* Ag = g_qT + ((size_t)b * NSEQ + n0) * CCH;
    const float* Bg = g_kT + ((size_t)b * NSEQ + m0) * CCH;
    for (int e4 = tid; e4 < 256 * 32; e4 += 256) {
        int r = e4 >> 5, c4 = e4 & 31;
        float4 va = *reinterpret_cast<const float4*>(Ag + r * CCH + c4 * 4);
        float* ap = As + (r & 127) * AS_STRIDE + (r >> 7);
        ap[(c4 * 4 + 0) * 2] = va.x; ap[(c4 * 4 + 1) * 2] = va.y;
        ap[(c4 * 4 + 2) * 2] = va.z; ap[(c4 * 4 + 3) * 2] = va.w;
        if (r < 128) {
            float4 vb = *reinterpret_cast<const float4*>(Bg + r * CCH + c4 * 4);
            *reinterpret_cast<float4*>(&Bs[r * 132 + c4 * 4]) = vb;
        }
    }
    __syncthreads();

    const int tx = tid & 15, tyy = tid >> 4;   // 16 x 16
    unsigned long long acc2[8][8];
#pragma unroll
    for (int i = 0; i < 8; i++)
#pragma unroll
        for (int j = 0; j < 8; j++) acc2[i][j] = 0ull;

#pragma unroll 1
    for (int k = 0; k < 128; k += 4) {
        float4 av[8][2];
#pragma unroll
        for (int i2 = 0; i2 < 8; i2++) {
            const float4* ap = reinterpret_cast<const float4*>(As + (tyy + 16 * i2) * AS_STRIDE + 2 * k);
            av[i2][0] = ap[0];
            av[i2][1] = ap[1];
        }
#pragma unroll
        for (int j = 0; j < 8; j++) {
            float4 bv = *reinterpret_cast<const float4*>(&Bs[(tx + 16 * j) * 132 + k]);
            unsigned long long b0 = pack2(bv.x, bv.x);
            unsigned long long b1 = pack2(bv.y, bv.y);
            unsigned long long b2 = pack2(bv.z, bv.z);
            unsigned long long b3 = pack2(bv.w, bv.w);
#pragma unroll
            for (int i2 = 0; i2 < 8; i2++) {
                const unsigned long long* a = reinterpret_cast<const unsigned long long*>(&av[i2][0]);
                fma2(acc2[i2][j], a[0], b0);
                fma2(acc2[i2][j], a[1], b1);
                fma2(acc2[i2][j], a[2], b2);
                fma2(acc2[i2][j], a[3], b3);
            }
        }
    }

    const float sc = sqrtf(128.0f);
    float* out = g_att + ((size_t)b * NSEQ + n0) * NSEQ + m0;
#pragma unroll
    for (int i2 = 0; i2 < 8; i2++)
#pragma unroll
        for (int j = 0; j < 8; j++) {
            float lo, hi;
            unpack2(acc2[i2][j], lo, hi);
            out[(size_t)(tyy + 16 * i2)       * NSEQ + tx + 16 * j] = __fdiv_rn(lo, sc);
            out[(size_t)(tyy + 16 * i2 + 128) * NSEQ + tx + 16 * j] = __fdiv_rn(hi, sc);
        }
}

// ---------------- K3: softmax rows in place; Kahan f32 row sum (16 rows/CTA) ----------------
__global__ __launch_bounds__(256) void softmax_kernel() {
    __shared__ float rowbuf[NSEQ];   // 32KB
    __shared__ float  redf[8];
    __shared__ double redd[8];
    __shared__ float  s_rmax, s_S;

    const int b   = blockIdx.y;
    const int r0  = blockIdx.x * 16;
    const int tid = threadIdx.x;
    const int lane = tid & 31, wid = tid >> 5;

    for (int rr = 0; rr < 16; rr++) {
        const int row = r0 + rr;
        float* L = g_att + ((size_t)b * NSEQ + row) * NSEQ;

        float lmax = -3.0e38f;
        for (int e4 = tid; e4 < NSEQ / 4; e4 += 256) {
            float4 v = *reinterpret_cast<const float4*>(L + e4 * 4);
            *reinterpret_cast<float4*>(&rowbuf[e4 * 4]) = v;
            lmax = fmaxf(lmax, fmaxf(fmaxf(v.x, v.y), fmaxf(v.z, v.w)));
        }
#pragma unroll
        for (int o = 16; o; o >>= 1) lmax = fmaxf(lmax, __shfl_xor_sync(0xffffffffu, lmax, o));
        if (lane == 0) redf[wid] = lmax;
        __syncthreads();
        if (tid == 0) {
            float m = redf[0];
#pragma unroll
            for (int w = 1; w < 8; w++) m = fmaxf(m, redf[w]);
            s_rmax = m;
        }
        __syncthreads();
        const float rm = s_rmax;

        float ksum = 0.f, kc = 0.f;
        for (int e4 = tid; e4 < NSEQ / 4; e4 += 256) {
            float4 v = *reinterpret_cast<float4*>(&rowbuf[e4 * 4]);
            v.x = expf(v.x - rm); v.y = expf(v.y - rm);
            v.z = expf(v.z - rm); v.w = expf(v.w - rm);
            *reinterpret_cast<float4*>(&rowbuf[e4 * 4]) = v;
#pragma unroll
            for (int u = 0; u < 4; u++) {
                float val = (&v.x)[u];
                float y = __fsub_rn(val, kc);
                float t = __fadd_rn(ksum, y);
                kc = __fsub_rn(__fsub_rn(t, ksum), y);
                ksum = t;
            }
        }
        double lsum = (double)ksum + (double)kc;
#pragma unroll
        for (int o = 16; o; o >>= 1) lsum += __shfl_xor_sync(0xffffffffu, lsum, o);
        if (lane == 0) redd[wid] = lsum;
        __syncthreads();
        if (tid == 0) {
            double s = redd[0];
#pragma unroll
            for (int w = 1; w < 8; w++) s += redd[w];
            s_S = (float)s;
        }
        __syncthreads();
        const float Sf = s_S;

        for (int e4 = tid; e4 < NSEQ / 4; e4 += 256) {
            float4 p = *reinterpret_cast<float4*>(&rowbuf[e4 * 4]);
            p.x = __fdiv_rn(p.x, Sf); p.y = __fdiv_rn(p.y, Sf);
            p.z = __fdiv_rn(p.z, Sf); p.w = __fdiv_rn(p.w, Sf);
            *reinterpret_cast<float4*>(L + e4 * 4) = p;
        }
        __syncthreads();
    }
}

// ---------------- K3b: XLA-GPU two-stage column reduction replica (DO NOT TOUCH) ----------------
__global__ __launch_bounds__(1024) void colsum_kernel() {
    __shared__ float part[32][33];
    const int b  = blockIdx.y;
    const int m  = blockIdx.x * 32 + threadIdx.x;
    const int ty = threadIdx.y;
    const float* A = g_att + (size_t)b * NSEQ * NSEQ + m;

    float s[8];
#pragma unroll
    for (int p = 0; p < 8; p++) {
        float acc = 0.f;
#pragma unroll
        for (int k = 0; k < 32; k++)
            acc += A[(size_t)(p * 1024 + ty + 32 * k) * NSEQ];
        s[p] = acc;
    }

    float s1[8];
#pragma unroll
    for (int p = 0; p < 8; p++) {
        __syncthreads();
        part[ty][threadIdx.x] = s[p];
        __syncthreads();
        float q = part[threadIdx.x][ty];
#pragma unroll
        for (int off = 16; off; off >>= 1)
            q += __shfl_down_sync(0xffffffffu, q, off);
        s1[p] = q;
    }

    if (threadIdx.x == 0) {
        float r = ((s1[0] + s1[4]) + (s1[2] + s1[6]))
                + ((s1[1] + s1[5]) + (s1[3] + s1[7]));
        g_sel[b * NSEQ + blockIdx.x * 32 + ty] = r;
    }
}

// ---------------- K4: top-k (bitonic sort, desc value / asc index tie-break) ----------------
#define K4_SMEM (NSEQ * 8)
__global__ __launch_bounds__(1024) void topk_kernel() {
    extern __shared__ unsigned long long keys[];
    const int b = blockIdx.x;
    const int tid = threadIdx.x;

    for (int e = tid; e < NSEQ; e += 1024) {
        unsigned int u = __float_as_uint(g_sel[b * NSEQ + e]);
        u = (u & 0x80000000u) ? ~u : (u | 0x80000000u);
        u = ~u;
        keys[e] = ((unsigned long long)u << 32) | (unsigned int)e;
    }
    __syncthreads();

    for (int size = 2; size <= NSEQ; size <<= 1) {
        for (int stride = size >> 1; stride > 0; stride >>= 1) {
            for (int i = tid; i < NSEQ; i += 1024) {
                int j = i ^ stride;
                if (j > i) {
                    bool up = ((i & size) == 0);
                    unsigned long long a = keys[i], c = keys[j];
                    if ((a > c) == up) { keys[i] = c; keys[j] = a; }
                }
            }
            __syncthreads();
        }
    }

    for (int e = tid; e < MSEL; e += 1024)
        g_idx[b * MSEL + e] = (int)(keys[e] & 0xffffffffu);
}

// ---------------- K5: out = P @ V^T via HMMA, 2-way bf16 split x 3 products ----------------
#define ORS   144
#define OTILE (128 * ORS)               // 18432 bytes
#define OUT_SMEM (4 * OTILE)            // 73728
__global__ __launch_bounds__(256, 2) void out_hmma_kernel() {
    extern __shared__ char smem[];
    const uint32_t base = smem_u32(smem);
    __shared__ int srow[128];
    const int tid = threadIdx.x, wid = tid >> 5, lane = tid & 31;
    const int z  = blockIdx.z;           // b*8 + ks
    const int b  = z >> 3;
    const int ks = z & 7;
    const int j0 = blockIdx.x * 128;

    if (tid < 128) srow[tid] = g_idx[b * MSEL + j0 + tid];
    __syncthreads();

    const int wm = wid >> 2, wn = wid & 3;     // warp tile: 64(c) x 32(j)
    float acc[4][4][4];
#pragma unroll
    for (int mt = 0; mt < 4; mt++)
#pragma unroll
        for (int nt = 0; nt < 4; nt++)
#pragma unroll
            for (int i = 0; i < 4; i++) acc[mt][nt][i] = 0.f;

    const float* vb = g_v + (size_t)b * CCH * NSEQ;
    const float* Ab = g_att + (size_t)b * NSEQ * NSEQ;

    const int a_row = lane & 15, a_ch = lane >> 4;
    const int b_row = lane & 7,  b_ch = (lane >> 3) & 1;

    const int kbeg = ks * (NSEQ / 8);
#pragma unroll 1
    for (int k0 = kbeg; k0 < kbeg + NSEQ / 8; k0 += 64) {
        for (int idx = tid; idx < 2048; idx += 256) {
            int row = idx >> 4, c4 = idx & 15;
            float4 v = *reinterpret_cast<const float4*>(vb + (size_t)row * NSEQ + k0 + c4 * 4);
            uint2 vhi, vlo;
            split4(v, vhi, vlo);
            *reinterpret_cast<uint2*>(smem + 0 * OTILE + row * ORS + c4 * 8) = vhi;
            *reinterpret_cast<uint2*>(smem + 1 * OTILE + row * ORS + c4 * 8) = vlo;
            float4 p = *reinterpret_cast<const float4*>(Ab + (size_t)srow[row] * NSEQ + k0 + c4 * 4);
            uint2 phi, plo;
            split4(p, phi, plo);
            *reinterpret_cast<uint2*>(smem + 2 * OTILE + row * ORS + c4 * 8) = phi;
            *reinterpret_cast<uint2*>(smem + 3 * OTILE + row * ORS + c4 * 8) = plo;
        }
        __syncthreads();

        const int PV[3] = {0, 0, 1};
        const int PP[3] = {0, 1, 0};
#pragma unroll
        for (int pp = 0; pp < 3; pp++) {
            const uint32_t Vb = base + PV[pp] * OTILE;
            const uint32_t Pb = base + (2 + PP[pp]) * OTILE;
#pragma unroll
            for (int kk = 0; kk < 4; kk++) {
                uint32_t af[4][4], bfr[4][2];
#pragma unroll
                for (int mt = 0; mt < 4; mt++)
                    ldsm_x4(af[mt], Vb + (wm * 64 + mt * 16 + a_row) * ORS + kk * 32 + a_ch * 16);
#pragma unroll
                for (int nt = 0; nt < 4; nt++)
                    ldsm_x2(bfr[nt], Pb + (wn * 32 + nt * 8 + b_row) * ORS + kk * 32 + b_ch * 16);
#pragma unroll
                for (int mt = 0; mt < 4; mt++)
#pragma unroll
                    for (int nt = 0; nt < 4; nt++)
                        mma_bf16(acc[mt][nt], af[mt], bfr[nt]);
            }
        }
        __syncthreads();
    }

    float* op = g_opart + (size_t)z * CCH * MSEL;
#pragma unroll
    for (int mt = 0; mt < 4; mt++)
#pragma unroll
        for (int nt = 0; nt < 4; nt++) {
            int c  = wm * 64 + mt * 16 + (lane >> 2);
            int jj = j0 + wn * 32 + nt * 8 + (lane & 3) * 2;
            *reinterpret_cast<float2*>(op + (size_t)c * MSEL + jj) =
                make_float2(acc[mt][nt][0], acc[mt][nt][1]);
            *reinterpret_cast<float2*>(op + (size_t)(c + 8) * MSEL + jj) =
                make_float2(acc[mt][nt][2], acc[mt][nt][3]);
        }
}

// ---------------- K5b: combine K-split partials (8-way) ----------------
__global__ __launch_bounds__(256) void combine_kernel(float* __restrict__ out) {
    const int b = blockIdx.y;
    const size_t e4 = (size_t)blockIdx.x * 256 + threadIdx.x;
    float4 r = make_float4(0.f, 0.f, 0.f, 0.f);
#pragma unroll
    for (int p = 0; p < 8; p++) {
        const float4 v = reinterpret_cast<const float4*>(
            g_opart + (size_t)(b * 8 + p) * CCH * MSEL)[e4];
        r.x += v.x; r.y += v.y; r.z += v.z; r.w += v.w;
    }
    reinterpret_cast<float4*>(out + (size_t)b * CCH * MSEL)[e4] = r;
}

// ---------------- launch ----------------
extern "C" void kernel_launch(void* const* d_in, const int* in_sizes, int n_in,
                              void* d_out, int out_size) {
    const float* x  = (const float*)d_in[0];
    const float* Wq = (const float*)d_in[1];
    const float* Wk = (const float*)d_in[2];
    const float* Wv = (const float*)d_in[3];
    float* out = (float*)d_out;

    cudaFuncSetAttribute(energy_kernel,   cudaFuncAttributeMaxDynamicSharedMemorySize, K2_SMEM);
    cudaFuncSetAttribute(topk_kernel,     cudaFuncAttributeMaxDynamicSharedMemorySize, K4_SMEM);
    cudaFuncSetAttribute(out_hmma_kernel, cudaFuncAttributeMaxDynamicSharedMemorySize, OUT_SMEM);

    dummy_kernel<<<1, 32>>>();                                                        // 1
    dummy_kernel<<<1, 32>>>();                                                        // 2
    dummy_kernel<<<1, 32>>>();                                                        // 3
    qkv_kernel<<<dim3(NSEQ / 64, BATCH), 256>>>(x, Wq, Wk, Wv);                       // 4 <- ncu slot
    energy_kernel<<<dim3(NSEQ / 128, NSEQ / 256, BATCH), 256, K2_SMEM>>>();           // 5
    softmax_kernel<<<dim3(NSEQ / 16, BATCH), 256>>>();                                // 6
    colsum_kernel<<<dim3(NSEQ / 32, BATCH), dim3(32, 32)>>>();                        // 7
    topk_kernel<<<BATCH, 1024, K4_SMEM>>>();                                          // 8
    out_hmma_kernel<<<dim3(MSEL / 128, 1, BATCH * 8), 256, OUT_SMEM>>>();             // 9
    combine_kernel<<<dim3(CCH * MSEL / 4 / 256, BATCH), 256>>>(out);                  // 10
}